// round 8
// baseline (speedup 1.0000x reference)
#include <cuda_runtime.h>
#include <cstdint>

// P=50000, H=W=28, CARD=50
// Inputs: p[50000] f32, I[784*50000] f32, J[784*50000] f32,
//         inds1[100*2] i32, inds2[100*2] i32
// Output: 200 f32

#define P_DIM    50000
#define W_IMG    28
#define N_OUT    200
#define ROW_F4   (P_DIM / 4)        // 12500 float4 per row
#define RPB      4                  // rows per block
#define NGROUPS  (N_OUT / RPB)      // 50
#define SPLIT    12
#define NBLOCKS  (NGROUPS * SPLIT)  // 600
#define NTHREADS 256
#define CHUNK_MAX 1042              // ceil(12500/12) float4
#define SEG_BYTES 16768             // CHUNK_MAX*16 rounded up to 128

// SMEM layout (dynamic): [0..8) mbar, [128 .. ) 5 segments (p, row0..row3)
#define SMEM_MBAR  0
#define SMEM_DATA  128
#define SMEM_TOTAL (SMEM_DATA + 5 * SEG_BYTES)   // 83968 B

__device__ float g_partial[N_OUT * SPLIT];
__device__ unsigned int g_done = 0;

__device__ __forceinline__ uint32_t smem_u32(const void* p_) {
    uint32_t a;
    asm("{ .reg .u64 t; cvta.to.shared.u64 t, %1; cvt.u32.u64 %0, t; }"
        : "=r"(a) : "l"(p_));
    return a;
}

__device__ __forceinline__ void bulk_g2s(uint32_t dst, const void* src,
                                         uint32_t bytes, uint32_t mbar) {
    asm volatile(
        "cp.async.bulk.shared::cluster.global.mbarrier::complete_tx::bytes "
        "[%0], [%1], %2, [%3];"
        :: "r"(dst), "l"(src), "r"(bytes), "r"(mbar) : "memory");
}

__device__ __forceinline__ float block_reduce(float v, float* ws) {
    #pragma unroll
    for (int off = 16; off > 0; off >>= 1)
        v += __shfl_down_sync(0xffffffffu, v, off);
    if ((threadIdx.x & 31) == 0) ws[threadIdx.x >> 5] = v;
    __syncthreads();
    float r = 0.0f;
    if (threadIdx.x < (NTHREADS / 32)) r = ws[threadIdx.x];
    if (threadIdx.x < 32) {
        #pragma unroll
        for (int off = (NTHREADS / 64); off > 0; off >>= 1)
            r += __shfl_down_sync(0xffu, r, off);
    }
    __syncthreads();
    return r;   // valid in thread 0
}

__global__ __launch_bounds__(NTHREADS)
void fused_tma_dot(const float* __restrict__ p,
                   const float* __restrict__ I,
                   const float* __restrict__ J,
                   const int*   __restrict__ inds1,
                   const int*   __restrict__ inds2,
                   float*       __restrict__ out) {
    extern __shared__ __align__(128) char smem[];
    const uint32_t smem_base = smem_u32(smem);
    const uint32_t mbar = smem_base + SMEM_MBAR;

    const int b   = blockIdx.x;
    const int g   = b / SPLIT;      // group 0..49 -> outputs 4g..4g+3
    const int c   = b % SPLIT;
    const int tid = threadIdx.x;

    const float* mat;
    const int*   inds;
    int jbase;
    if (g < NGROUPS / 2) { mat = I; inds = inds1; jbase = g * RPB; }
    else                 { mat = J; inds = inds2; jbase = g * RPB - 100; }

    const int start = (c * ROW_F4) / SPLIT;          // float4 units
    const int end   = ((c + 1) * ROW_F4) / SPLIT;
    const int len   = end - start;
    const uint32_t bytes = (uint32_t)len * 16u;

    if (tid == 0) {
        asm volatile("mbarrier.init.shared.b64 [%0], 1;" :: "r"(mbar) : "memory");
    }
    __syncthreads();

    if (tid == 0) {
        asm volatile("mbarrier.arrive.expect_tx.shared.b64 _, [%0], %1;"
                     :: "r"(mbar), "r"(bytes * 5u) : "memory");
        // p chunk -> segment 0
        bulk_g2s(smem_base + SMEM_DATA, p + (size_t)start * 4, bytes, mbar);
        // 4 gathered rows -> segments 1..4
        #pragma unroll
        for (int u = 0; u < RPB; u++) {
            int j  = jbase + u;
            int rr = inds[2 * j + 0];
            int cc = inds[2 * j + 1];
            const float* src = mat + (size_t)(rr * W_IMG + cc) * P_DIM
                                   + (size_t)start * 4;
            bulk_g2s(smem_base + SMEM_DATA + (u + 1) * SEG_BYTES, src, bytes, mbar);
        }
    }

    // wait for all 5 copies (phase 0)
    {
        uint32_t done;
        asm volatile(
            "{\n\t.reg .pred P;\n\t"
            "mbarrier.try_wait.parity.shared.b64 P, [%1], 0;\n\t"
            "selp.b32 %0, 1, 0, P;\n\t}"
            : "=r"(done) : "r"(mbar) : "memory");
        while (!done) {
            asm volatile(
                "{\n\t.reg .pred P;\n\t"
                "mbarrier.try_wait.parity.shared.b64 P, [%1], 0, 0x989680;\n\t"
                "selp.b32 %0, 1, 0, P;\n\t}"
                : "=r"(done) : "r"(mbar) : "memory");
        }
    }

    const float4* p_s  = reinterpret_cast<const float4*>(smem + SMEM_DATA);
    const float4* r0_s = reinterpret_cast<const float4*>(smem + SMEM_DATA + 1 * SEG_BYTES);
    const float4* r1_s = reinterpret_cast<const float4*>(smem + SMEM_DATA + 2 * SEG_BYTES);
    const float4* r2_s = reinterpret_cast<const float4*>(smem + SMEM_DATA + 3 * SEG_BYTES);
    const float4* r3_s = reinterpret_cast<const float4*>(smem + SMEM_DATA + 4 * SEG_BYTES);

    float a0 = 0.0f, a1 = 0.0f, a2 = 0.0f, a3 = 0.0f;
    for (int i = tid; i < len; i += NTHREADS) {
        float4 q  = p_s[i];
        float4 v0 = r0_s[i];
        float4 v1 = r1_s[i];
        float4 v2 = r2_s[i];
        float4 v3 = r3_s[i];
        a0 += v0.x * q.x + v0.y * q.y + v0.z * q.z + v0.w * q.w;
        a1 += v1.x * q.x + v1.y * q.y + v1.z * q.z + v1.w * q.w;
        a2 += v2.x * q.x + v2.y * q.y + v2.z * q.z + v2.w * q.w;
        a3 += v3.x * q.x + v3.y * q.y + v3.z * q.z + v3.w * q.w;
    }

    __shared__ float ws[NTHREADS / 32];
    __shared__ bool  s_last;

    float t0 = block_reduce(a0, ws);
    float t1 = block_reduce(a1, ws);
    float t2 = block_reduce(a2, ws);
    float t3 = block_reduce(a3, ws);

    if (tid == 0) {
        int ob = g * RPB;
        g_partial[(ob + 0) * SPLIT + c] = t0;
        g_partial[(ob + 1) * SPLIT + c] = t1;
        g_partial[(ob + 2) * SPLIT + c] = t2;
        g_partial[(ob + 3) * SPLIT + c] = t3;
        __threadfence();
        unsigned int prev = atomicAdd(&g_done, 1u);
        s_last = (prev == NBLOCKS - 1);
    }
    __syncthreads();

    if (s_last) {
        int oo = tid;
        if (oo < N_OUT) {
            float s = 0.0f;
            #pragma unroll
            for (int k = 0; k < SPLIT; k++) s += g_partial[oo * SPLIT + k];
            out[oo] = s;
        }
        if (tid == 0) g_done = 0;
    }
}

extern "C" void kernel_launch(void* const* d_in, const int* in_sizes, int n_in,
                              void* d_out, int out_size) {
    const float* p     = (const float*)d_in[0];
    const float* I     = (const float*)d_in[1];
    const float* J     = (const float*)d_in[2];
    const int*   inds1 = (const int*)d_in[3];
    const int*   inds2 = (const int*)d_in[4];
    float* out = (float*)d_out;

    static bool attr_set = false;
    if (!attr_set) {
        cudaFuncSetAttribute(fused_tma_dot,
                             cudaFuncAttributeMaxDynamicSharedMemorySize,
                             SMEM_TOTAL);
        attr_set = true;
    }

    fused_tma_dot<<<NBLOCKS, NTHREADS, SMEM_TOTAL>>>(p, I, J, inds1, inds2, out);
}

// round 9
// speedup vs baseline: 1.3459x; 1.3459x over previous
#include <cuda_runtime.h>

// P=50000, H=W=28, CARD=50
// Inputs: p[50000] f32, I[784*50000] f32, J[784*50000] f32,
//         inds1[100*2] i32, inds2[100*2] i32
// Output: 200 f32

#define P_DIM    50000
#define W_IMG    28
#define N_OUT    200
#define ROW_F4   (P_DIM / 4)          // 12500 float4 per row
#define RPB      4                    // rows (outputs) per block
#define NGROUPS  (N_OUT / RPB)        // 50
#define CHUNK_F4 1024                 // float4 per chunk (4 per thread)
#define NCHUNK   13                   // ceil(12500/1024)
#define NBLOCKS  (NGROUPS * NCHUNK)   // 650
#define NTHREADS 256
#define KITER    4                    // float4 per thread per segment

__device__ float g_partial[N_OUT * NCHUNK];
__device__ unsigned int g_done = 0;

__device__ __forceinline__ float block_reduce(float v, float* ws) {
    #pragma unroll
    for (int off = 16; off > 0; off >>= 1)
        v += __shfl_down_sync(0xffffffffu, v, off);
    if ((threadIdx.x & 31) == 0) ws[threadIdx.x >> 5] = v;
    __syncthreads();
    float r = 0.0f;
    if (threadIdx.x < (NTHREADS / 32)) r = ws[threadIdx.x];
    if (threadIdx.x < 32) {
        #pragma unroll
        for (int off = (NTHREADS / 64); off > 0; off >>= 1)
            r += __shfl_down_sync(0xffu, r, off);
    }
    __syncthreads();
    return r;   // valid in thread 0
}

__global__ __launch_bounds__(NTHREADS)
void fused_batch_dot(const float* __restrict__ p,
                     const float* __restrict__ I,
                     const float* __restrict__ J,
                     const int*   __restrict__ inds1,
                     const int*   __restrict__ inds2,
                     float*       __restrict__ out) {
    const int b   = blockIdx.x;
    const int g   = b / NCHUNK;     // group -> outputs 4g..4g+3
    const int c   = b % NCHUNK;     // chunk
    const int tid = threadIdx.x;

    const float* mat;
    const int*   inds;
    int jbase;
    if (g < NGROUPS / 2) { mat = I; inds = inds1; jbase = g * RPB; }
    else                 { mat = J; inds = inds2; jbase = g * RPB - 100; }

    const float4* r4[RPB];
    #pragma unroll
    for (int u = 0; u < RPB; u++) {
        int j  = jbase + u;
        int rr = inds[2 * j + 0];
        int cc = inds[2 * j + 1];
        r4[u] = reinterpret_cast<const float4*>(mat) +
                (size_t)(rr * W_IMG + cc) * ROW_F4;
    }
    const float4* p4 = reinterpret_cast<const float4*>(p);

    const int start = c * CHUNK_F4;
    const int end   = (start + CHUNK_F4 < ROW_F4) ? (start + CHUNK_F4) : ROW_F4;

    const float4 z4 = make_float4(0.f, 0.f, 0.f, 0.f);

    // ---- front-batched loads: 20 independent LDG.128 ----
    float4 q[KITER];
    float4 v[RPB][KITER];
    #pragma unroll
    for (int k = 0; k < KITER; k++) {
        int i = start + tid + k * NTHREADS;
        bool ok = (i < end);
        q[k] = ok ? p4[i] : z4;
        #pragma unroll
        for (int u = 0; u < RPB; u++)
            v[u][k] = ok ? r4[u][i] : z4;
    }

    // ---- all FMAs after loads ----
    float a[RPB] = {0.f, 0.f, 0.f, 0.f};
    #pragma unroll
    for (int k = 0; k < KITER; k++) {
        #pragma unroll
        for (int u = 0; u < RPB; u++) {
            a[u] += v[u][k].x * q[k].x + v[u][k].y * q[k].y
                  + v[u][k].z * q[k].z + v[u][k].w * q[k].w;
        }
    }

    __shared__ float ws[NTHREADS / 32];
    __shared__ bool  s_last;

    float t0 = block_reduce(a[0], ws);
    float t1 = block_reduce(a[1], ws);
    float t2 = block_reduce(a[2], ws);
    float t3 = block_reduce(a[3], ws);

    if (tid == 0) {
        int ob = g * RPB;
        g_partial[(ob + 0) * NCHUNK + c] = t0;
        g_partial[(ob + 1) * NCHUNK + c] = t1;
        g_partial[(ob + 2) * NCHUNK + c] = t2;
        g_partial[(ob + 3) * NCHUNK + c] = t3;
        __threadfence();
        unsigned int prev = atomicAdd(&g_done, 1u);
        s_last = (prev == NBLOCKS - 1);
    }
    __syncthreads();

    if (s_last) {
        int oo = tid;
        if (oo < N_OUT) {
            float s = 0.0f;
            #pragma unroll
            for (int k = 0; k < NCHUNK; k++) s += g_partial[oo * NCHUNK + k];
            out[oo] = s;
        }
        if (tid == 0) g_done = 0;   // reset for next graph replay
    }
}

extern "C" void kernel_launch(void* const* d_in, const int* in_sizes, int n_in,
                              void* d_out, int out_size) {
    const float* p     = (const float*)d_in[0];
    const float* I     = (const float*)d_in[1];
    const float* J     = (const float*)d_in[2];
    const int*   inds1 = (const int*)d_in[3];
    const int*   inds2 = (const int*)d_in[4];
    float* out = (float*)d_out;

    fused_batch_dot<<<NBLOCKS, NTHREADS>>>(p, I, J, inds1, inds2, out);
}